// round 8
// baseline (speedup 1.0000x reference)
#include <cuda_runtime.h>
#include <cuda_fp16.h>
#include <cstdint>

#define BATCH 8
#define CIN   128
#define COUT  128
#define RES   256
#define WDIM  512
#define CH    16      // ci per chunk
#define NCH   8       // chunks

// ---------------- device scratch ----------------
__device__ float  g_styles[BATCH * CIN];
__device__ float  g_w2[COUT * CIN];
__device__ float  g_dcoef[BATCH * COUT];
// folded fp16 weights: [b][cc(8)][tap(9)][co(128)][ci16(16)]
__device__ __half g_wf[BATCH * NCH * 9 * COUT * CH];
// fp16 chunked-NHWC input: [b][cc(8)][h][w][ci16(16)]
__device__ __half g_xh[(size_t)BATCH * NCH * RES * RES * CH];

// ---------------- prologue kernels (verified R4/R6) ----------------
__global__ void k_styles(const float* __restrict__ w,
                         const float* __restrict__ aw,
                         const float* __restrict__ ab) {
    int b = blockIdx.x, i = threadIdx.x;
    float s = 0.f;
    const float* wr = w + b * WDIM;
    const float* ar = aw + i * WDIM;
    for (int d = 0; d < WDIM; d++) s += wr[d] * ar[d];
    g_styles[b * CIN + i] = s * 0.04419417382415922f + ab[i];
}

__global__ void k_w2(const float* __restrict__ wt) {
    int idx = blockIdx.x * blockDim.x + threadIdx.x;
    if (idx >= COUT * CIN) return;
    const float* p = wt + idx * 9;
    float s = 0.f;
    #pragma unroll
    for (int t = 0; t < 9; t++) { float v = p[t]; s += v * v; }
    g_w2[idx] = s;
}

__global__ void k_dcoef() {
    int b = blockIdx.x, o = threadIdx.x;
    float s = 0.f;
    for (int i = 0; i < CIN; i++) {
        float st = g_styles[b * CIN + i];
        s += g_w2[o * CIN + i] * st * st;
    }
    g_dcoef[b * COUT + o] = rsqrtf(s + 1e-8f);
}

__global__ void k_fold(const float* __restrict__ wt) {
    int idx = blockIdx.x * blockDim.x + threadIdx.x;
    if (idx >= BATCH * NCH * 9 * COUT * CH) return;
    int ci16 = idx & 15;
    int co   = (idx >> 4) & 127;
    int rest = idx >> 11;
    int tap  = rest % 9;
    int bcc  = rest / 9;
    int cc   = bcc & 7;
    int b    = bcc >> 3;
    int ci   = cc * CH + ci16;
    float v = wt[(co * CIN + ci) * 9 + tap] * g_styles[b * CIN + ci] * g_dcoef[b * COUT + co];
    g_wf[idx] = __float2half(v);
}

// NCHW fp32 -> chunked NHWC fp16. Block: (ci 128 x w 32) for one (b,h).
__global__ __launch_bounds__(256, 1) void k_half(const float* __restrict__ x) {
    __shared__ float s[32][132];   // [w][ci]
    int b = blockIdx.z, h = blockIdx.y, w0 = blockIdx.x * 32;
    int tid = threadIdx.x;
    {
        int ci = tid >> 1, wseg = (tid & 1) * 16;
        const float* src = x + (((size_t)(b * CIN + ci) * RES + h) * RES + w0 + wseg);
        #pragma unroll
        for (int j = 0; j < 4; j++) {
            float4 v = *((const float4*)(src + j * 4));
            s[wseg + j * 4 + 0][ci] = v.x;
            s[wseg + j * 4 + 1][ci] = v.y;
            s[wseg + j * 4 + 2][ci] = v.z;
            s[wseg + j * 4 + 3][ci] = v.w;
        }
    }
    __syncthreads();
    {
        int wl = tid >> 3, cc = tid & 7;
        __half hv[16];
        #pragma unroll
        for (int j = 0; j < 4; j++) {
            float4 v = *((const float4*)(&s[wl][cc * 16 + j * 4]));
            hv[j * 4 + 0] = __float2half(v.x);
            hv[j * 4 + 1] = __float2half(v.y);
            hv[j * 4 + 2] = __float2half(v.z);
            hv[j * 4 + 3] = __float2half(v.w);
        }
        __half* dst = g_xh + ((((size_t)(b * NCH + cc) * RES + h) * RES + (w0 + wl)) * CH);
        *((uint4*)dst)       = *((uint4*)hv);
        *((uint4*)(dst + 8)) = *((uint4*)(hv + 8));
    }
}

// ---------------- mma helpers ----------------
__device__ __forceinline__ uint32_t smem_u32(const void* p) {
    uint32_t a;
    asm("{ .reg .u64 t; cvta.to.shared.u64 t, %1; cvt.u32.u64 %0, t; }" : "=r"(a) : "l"(p));
    return a;
}
__device__ __forceinline__ void ldsm_x4(uint32_t* r, uint32_t addr) {
    asm volatile("ldmatrix.sync.aligned.m8n8.x4.shared.b16 {%0,%1,%2,%3}, [%4];"
                 : "=r"(r[0]), "=r"(r[1]), "=r"(r[2]), "=r"(r[3]) : "r"(addr));
}
__device__ __forceinline__ void mma16816(float* c, const uint32_t* a, uint32_t b0, uint32_t b1) {
    asm volatile(
        "mma.sync.aligned.m16n8k16.row.col.f32.f16.f16.f32 "
        "{%0,%1,%2,%3},{%4,%5,%6,%7},{%8,%9},{%0,%1,%2,%3};"
        : "+f"(c[0]), "+f"(c[1]), "+f"(c[2]), "+f"(c[3])
        : "r"(a[0]), "r"(a[1]), "r"(a[2]), "r"(a[3]), "r"(b0), "r"(b1));
}
__device__ __forceinline__ void cpa16(uint32_t dst, const void* src, int sz) {
    asm volatile("cp.async.cg.shared.global [%0], [%1], 16, %2;\n"
                 :: "r"(dst), "l"(src), "r"(sz));
}
__device__ __forceinline__ void cpa_commit() { asm volatile("cp.async.commit_group;\n"); }

// ---------------- conv smem layout ----------------
// input  buf: 3 kh-rows x 130 px x 16 halves, row stride 48 B -> 18,720 B each
// weight buf: 576 rows (tap*64+co64) x 16 halves, stride 48 B ->  27,648 B each
// [in0][in1][w0][w1] = 2*18720 + 2*27648 = 92,736 B
// s_epi float[64][132] = 33,792 B overlays for epilogue
#define IN_BUF_B  18720
#define W_BUF_B   27648
#define W_OFF_B   37440
#define SMEM_BYTES 92736

__device__ __forceinline__ void issue_chunk(
    int cc, int buf, int tid, int h, int w0, int n0,
    uint32_t s_in_u, uint32_t s_w_u,
    const __half* __restrict__ xh_b, const __half* __restrict__ wf_b)
{
    // weights: 576 rows (tap,64-co slice) x 2 segs = 1152 x 16B; 9 per thread
    const __half* wsrc = wf_b + (size_t)cc * (9 * COUT * CH);
    uint32_t wdst = s_w_u + buf * W_BUF_B;
    #pragma unroll
    for (int j = 0; j < 9; j++) {
        int i = tid + j * 128;            // 0..1151
        int row = i >> 1, seg = i & 1;    // row = tap*64 + col
        int tap = row >> 6, col = row & 63;
        cpa16(wdst + row * 48 + seg * 16,
              wsrc + ((size_t)(tap * 128 + n0 + col) * CH) + seg * 8, 16);
    }
    // input: 3 rows x 130 cols x 2 segs = 780 x 16B; 7 per thread (guarded)
    const __half* xs = xh_b + (size_t)cc * (RES * RES * CH);
    uint32_t idst = s_in_u + buf * IN_BUF_B;
    #pragma unroll
    for (int j = 0; j < 7; j++) {
        int i = tid + j * 128;
        if (i < 780) {
            int row = i >> 1, seg = i & 1;
            int kh = row / 130;
            int c  = row - kh * 130;
            int gr = h + kh - 1, gc = w0 + c - 1;
            bool ok = ((unsigned)gr < RES) && ((unsigned)gc < RES);
            const __half* src = ok
                ? (xs + ((size_t)gr * RES + gc) * CH + seg * 8)
                : xs;
            cpa16(idst + row * 48 + seg * 16, src, ok ? 16 : 0);
        }
    }
}

__global__ __launch_bounds__(128, 2)
void k_conv(const float* __restrict__ noise,
            const float* __restrict__ nstr,
            const float* __restrict__ bias,
            float* __restrict__ out) {
    extern __shared__ char smem[];
    float* s_epi = (float*)smem;

    const int w0  = (blockIdx.x & 1) * 128;   // pixel-column tile
    const int n0  = (blockIdx.x >> 1) * 64;   // cout tile
    const int h   = blockIdx.y;
    const int b   = blockIdx.z;
    const int tid = threadIdx.x;
    const int wm  = tid >> 5, lane = tid & 31;  // warp = pixel group (32 px each)

    const uint32_t s_in_u = smem_u32(smem);
    const uint32_t s_w_u  = s_in_u + W_OFF_B;
    const __half* xh_b = g_xh + (size_t)b * (NCH * RES * RES * CH);
    const __half* wf_b = g_wf + (size_t)b * (NCH * 9 * COUT * CH);

    float acc[2][8][4];
    #pragma unroll
    for (int a = 0; a < 2; a++)
        #pragma unroll
        for (int j = 0; j < 8; j++)
            #pragma unroll
            for (int c = 0; c < 4; c++) acc[a][j][c] = 0.f;

    issue_chunk(0, 0, tid, h, w0, n0, s_in_u, s_w_u, xh_b, wf_b);
    cpa_commit();

    // per-lane ldmatrix base addresses
    const uint32_t a_lane = s_in_u + (uint32_t)((wm * 32 + (lane & 15)) * 48 + ((lane >> 4) << 4));
    const uint32_t b_lane = s_w_u  + (uint32_t)(((lane & 15)) * 48 + ((lane >> 4) << 4));

    #pragma unroll 1
    for (int cc = 0; cc < NCH; cc++) {
        if (cc < NCH - 1) {
            issue_chunk(cc + 1, (cc + 1) & 1, tid, h, w0, n0, s_in_u, s_w_u, xh_b, wf_b);
            cpa_commit();
            asm volatile("cp.async.wait_group 1;\n");
        } else {
            asm volatile("cp.async.wait_group 0;\n");
        }
        __syncthreads();

        const uint32_t ab = a_lane + (cc & 1) * IN_BUF_B;
        const uint32_t bb = b_lane + (cc & 1) * W_BUF_B;
        #pragma unroll
        for (int tap = 0; tap < 9; tap++) {
            const int kh = tap / 3, kw = tap % 3;
            const uint32_t arow = ab + (uint32_t)(kh * 130 + kw) * 48;
            const uint32_t brow = bb + (uint32_t)tap * 3072;   // 64 rows * 48 B
            uint32_t af[2][4], bf[4][4];
            #pragma unroll
            for (int mi = 0; mi < 2; mi++) ldsm_x4(af[mi], arow + mi * 768);   // +16 rows
            #pragma unroll
            for (int ni = 0; ni < 4; ni++) ldsm_x4(bf[ni], brow + ni * 768);
            #pragma unroll
            for (int mi = 0; mi < 2; mi++)
                #pragma unroll
                for (int ni = 0; ni < 4; ni++) {
                    mma16816(acc[mi][ni * 2],     af[mi], bf[ni][0], bf[ni][2]);
                    mma16816(acc[mi][ni * 2 + 1], af[mi], bf[ni][1], bf[ni][3]);
                }
        }
        __syncthreads();
    }

    // ---------------- epilogue (R4-verified mapping, 64-cout slice) ----------------
    const float ns = nstr[0];
    const float* nrow = noise + (size_t)h * RES + w0;
    const float SQ2 = 1.4142135623730951f;

    #pragma unroll
    for (int mi = 0; mi < 2; mi++) {
        int p0 = wm * 32 + mi * 16 + (lane >> 2);
        float nv0 = nrow[p0] * ns;
        float nv1 = nrow[p0 + 8] * ns;
        #pragma unroll
        for (int j = 0; j < 8; j++) {
            int col = j * 8 + (lane & 3) * 2;          // local cout 0..63
            float b0 = bias[n0 + col], b1 = bias[n0 + col + 1];
            float* a = acc[mi][j];
            float v;
            v = a[0] + nv0 + b0; v = (v >= 0.f) ? v : 0.2f * v; v *= SQ2;
            s_epi[col * 132 + p0] = fminf(fmaxf(v, -256.f), 256.f);
            v = a[1] + nv0 + b1; v = (v >= 0.f) ? v : 0.2f * v; v *= SQ2;
            s_epi[(col + 1) * 132 + p0] = fminf(fmaxf(v, -256.f), 256.f);
            v = a[2] + nv1 + b0; v = (v >= 0.f) ? v : 0.2f * v; v *= SQ2;
            s_epi[col * 132 + p0 + 8] = fminf(fmaxf(v, -256.f), 256.f);
            v = a[3] + nv1 + b1; v = (v >= 0.f) ? v : 0.2f * v; v *= SQ2;
            s_epi[(col + 1) * 132 + p0 + 8] = fminf(fmaxf(v, -256.f), 256.f);
        }
    }
    __syncthreads();

    // coalesced writeout: 2 threads per cout row, 64 floats each
    {
        int col = tid >> 1;
        int off = (tid & 1) * 64;
        float* dst = out + (((size_t)(b * COUT + n0 + col)) * RES + h) * RES + w0 + off;
        const float* sp = s_epi + col * 132 + off;
        #pragma unroll
        for (int q = 0; q < 64; q += 4)
            *((float4*)(dst + q)) = *((const float4*)(sp + q));
    }
}

// ---------------- launch ----------------
extern "C" void kernel_launch(void* const* d_in, const int* in_sizes, int n_in,
                              void* d_out, int out_size) {
    const float* x     = (const float*)d_in[0];
    const float* w     = (const float*)d_in[1];
    const float* aw    = (const float*)d_in[2];
    const float* ab    = (const float*)d_in[3];
    const float* wt    = (const float*)d_in[4];
    const float* noise = (const float*)d_in[5];
    const float* nstr  = (const float*)d_in[6];
    const float* bias  = (const float*)d_in[7];
    float* out = (float*)d_out;

    k_styles<<<BATCH, CIN>>>(w, aw, ab);
    k_w2<<<(COUT * CIN + 255) / 256, 256>>>(wt);
    k_dcoef<<<BATCH, COUT>>>();
    k_fold<<<(BATCH * NCH * 9 * COUT * CH + 255) / 256, 256>>>(wt);

    dim3 hgrid(RES / 32, RES, BATCH);
    k_half<<<hgrid, 256>>>(x);

    cudaFuncSetAttribute(k_conv, cudaFuncAttributeMaxDynamicSharedMemorySize, SMEM_BYTES);
    dim3 grid(4, RES, BATCH);
    k_conv<<<grid, 128, SMEM_BYTES>>>(noise, nstr, bias, out);
}

// round 9
// speedup vs baseline: 1.1285x; 1.1285x over previous
#include <cuda_runtime.h>
#include <cuda_fp16.h>
#include <cstdint>

#define BATCH 8
#define CIN   128
#define COUT  128
#define RES   256
#define WDIM  512
#define CH    16      // ci per chunk
#define NCH   8       // chunks

// ---------------- device scratch ----------------
__device__ float  g_styles[BATCH * CIN];
__device__ float  g_w2[COUT * CIN];
// folded fp16 weights: [b][cc(8)][tap(9)][co(128)][ci16(16)]
__device__ __half g_wf[BATCH * NCH * 9 * COUT * CH];
// fp16 chunked-NHWC input: [b][cc(8)][h][w][ci16(16)]
__device__ __half g_xh[(size_t)BATCH * NCH * RES * RES * CH];

// ---------------- prologue kernel 1: styles (blocks 0-7) + w2 (blocks 8-71) ----
__global__ __launch_bounds__(256, 1) void k_sw(const float* __restrict__ w,
                                               const float* __restrict__ aw,
                                               const float* __restrict__ ab,
                                               const float* __restrict__ wt) {
    int blk = blockIdx.x;
    int tid = threadIdx.x;
    if (blk < 8) {
        if (tid < CIN) {
            int b = blk, i = tid;
            float s = 0.f;
            const float* wr = w + b * WDIM;
            const float* ar = aw + i * WDIM;
            for (int d = 0; d < WDIM; d++) s += wr[d] * ar[d];
            g_styles[b * CIN + i] = s * 0.04419417382415922f + ab[i];
        }
    } else {
        int idx = (blk - 8) * 256 + tid;   // o*CIN + i, 16384 total
        const float* p = wt + idx * 9;
        float s = 0.f;
        #pragma unroll
        for (int t = 0; t < 9; t++) { float v = p[t]; s += v * v; }
        g_w2[idx] = s;
    }
}

// ---------------- prologue kernel 2: dcoef + fold fused. Block=(b,o). ----------
__global__ __launch_bounds__(128, 8) void k_fold2(const float* __restrict__ wt) {
    __shared__ float red[128];
    __shared__ float s_style[128];
    __shared__ float s_dcoef;
    const int b = blockIdx.x >> 7;
    const int o = blockIdx.x & 127;
    const int t = threadIdx.x;

    float st = g_styles[b * CIN + t];
    s_style[t] = st;
    red[t] = g_w2[o * CIN + t] * st * st;
    __syncthreads();
    #pragma unroll
    for (int off = 64; off > 0; off >>= 1) {
        if (t < off) red[t] += red[t + off];
        __syncthreads();
    }
    if (t == 0) s_dcoef = rsqrtf(red[0] + 1e-8f);
    __syncthreads();
    const float dc = s_dcoef;

    // fold: 1152 values for this (b,o): cc(8) x tap(9) x ci16(16)
    const int ci16 = t & 15;
    const int g0   = t >> 4;            // 0..7
    #pragma unroll
    for (int j = 0; j < 9; j++) {
        int pair = g0 + j * 8;          // 0..71
        int cc  = pair / 9;
        int tap = pair - cc * 9;
        int ci  = cc * CH + ci16;
        float v = wt[(o * CIN + ci) * 9 + tap] * s_style[ci] * dc;
        g_wf[((((size_t)(b * NCH + cc) * 9 + tap) * COUT + o) * CH) + ci16] = __float2half(v);
    }
}

// NCHW fp32 -> chunked NHWC fp16. Block: (ci 128 x w 32) for one (b,h).
__global__ __launch_bounds__(256, 1) void k_half(const float* __restrict__ x) {
    __shared__ float s[32][132];   // [w][ci]
    int b = blockIdx.z, h = blockIdx.y, w0 = blockIdx.x * 32;
    int tid = threadIdx.x;
    {
        int ci = tid >> 1, wseg = (tid & 1) * 16;
        const float* src = x + (((size_t)(b * CIN + ci) * RES + h) * RES + w0 + wseg);
        #pragma unroll
        for (int j = 0; j < 4; j++) {
            float4 v = *((const float4*)(src + j * 4));
            s[wseg + j * 4 + 0][ci] = v.x;
            s[wseg + j * 4 + 1][ci] = v.y;
            s[wseg + j * 4 + 2][ci] = v.z;
            s[wseg + j * 4 + 3][ci] = v.w;
        }
    }
    __syncthreads();
    {
        int wl = tid >> 3, cc = tid & 7;
        __half hv[16];
        #pragma unroll
        for (int j = 0; j < 4; j++) {
            float4 v = *((const float4*)(&s[wl][cc * 16 + j * 4]));
            hv[j * 4 + 0] = __float2half(v.x);
            hv[j * 4 + 1] = __float2half(v.y);
            hv[j * 4 + 2] = __float2half(v.z);
            hv[j * 4 + 3] = __float2half(v.w);
        }
        __half* dst = g_xh + ((((size_t)(b * NCH + cc) * RES + h) * RES + (w0 + wl)) * CH);
        *((uint4*)dst)       = *((uint4*)hv);
        *((uint4*)(dst + 8)) = *((uint4*)(hv + 8));
    }
}

// ---------------- mma helpers ----------------
__device__ __forceinline__ uint32_t smem_u32(const void* p) {
    uint32_t a;
    asm("{ .reg .u64 t; cvta.to.shared.u64 t, %1; cvt.u32.u64 %0, t; }" : "=r"(a) : "l"(p));
    return a;
}
__device__ __forceinline__ void ldsm_x4(uint32_t* r, uint32_t addr) {
    asm volatile("ldmatrix.sync.aligned.m8n8.x4.shared.b16 {%0,%1,%2,%3}, [%4];"
                 : "=r"(r[0]), "=r"(r[1]), "=r"(r[2]), "=r"(r[3]) : "r"(addr));
}
__device__ __forceinline__ void mma16816(float* c, const uint32_t* a, uint32_t b0, uint32_t b1) {
    asm volatile(
        "mma.sync.aligned.m16n8k16.row.col.f32.f16.f16.f32 "
        "{%0,%1,%2,%3},{%4,%5,%6,%7},{%8,%9},{%0,%1,%2,%3};"
        : "+f"(c[0]), "+f"(c[1]), "+f"(c[2]), "+f"(c[3])
        : "r"(a[0]), "r"(a[1]), "r"(a[2]), "r"(a[3]), "r"(b0), "r"(b1));
}
__device__ __forceinline__ void cpa16(uint32_t dst, const void* src, int sz) {
    asm volatile("cp.async.cg.shared.global [%0], [%1], 16, %2;\n"
                 :: "r"(dst), "l"(src), "r"(sz));
}
__device__ __forceinline__ void cpa_commit() { asm volatile("cp.async.commit_group;\n"); }

// ---------------- conv smem layout (R6, unchanged) ----------------
#define IN_BUF_B  24960
#define W_BUF_B   55296
#define W_OFF_B   49920
#define SMEM_BYTES 160512

__device__ __forceinline__ void issue_chunk(
    int cc, int buf, int tid, int h0, int w0,
    uint32_t s_in_u, uint32_t s_w_u,
    const __half* __restrict__ xh_b, const __half* __restrict__ wf_b)
{
    const __half* wsrc = wf_b + (size_t)cc * (9 * COUT * CH);
    uint32_t wdst = s_w_u + buf * W_BUF_B;
    #pragma unroll
    for (int j = 0; j < 9; j++) {
        int i = tid + j * 256;            // 0..2303
        int row = i >> 1, seg = i & 1;
        cpa16(wdst + row * 48 + seg * 16, wsrc + i * 8, 16);
    }
    const __half* xh_cc = xh_b + (size_t)cc * (RES * RES * CH);
    uint32_t idst = s_in_u + buf * IN_BUF_B;
    #pragma unroll
    for (int j = 0; j < 5; j++) {
        int i = tid + j * 256;
        if (i < 1040) {
            int row = i >> 1, seg = i & 1;
            int kh = row / 130;
            int c  = row - kh * 130;
            int gr = h0 + kh - 1, gc = w0 + c - 1;
            bool ok = ((unsigned)gr < RES) && ((unsigned)gc < RES);
            const __half* src = ok
                ? (xh_cc + ((size_t)gr * RES + gc) * CH + seg * 8)
                : xh_cc;
            cpa16(idst + row * 48 + seg * 16, src, ok ? 16 : 0);
        }
    }
}

__global__ __launch_bounds__(256, 1)
void k_conv(const float* __restrict__ noise,
            const float* __restrict__ nstr,
            const float* __restrict__ bias,
            float* __restrict__ out) {
    extern __shared__ char smem[];
    float* s_epi = (float*)smem;

    const int w0  = blockIdx.x * 128;
    const int h0  = blockIdx.y * 2;     // two output rows per block
    const int b   = blockIdx.z;
    const int tid = threadIdx.x;
    const int warp = tid >> 5, lane = tid & 31;
    const int wm = warp >> 1;
    const int wn = warp & 1;
    const int wr = wm >> 1;
    const int wc = wm & 1;

    const uint32_t s_in_u = smem_u32(smem);
    const uint32_t s_w_u  = s_in_u + W_OFF_B;
    const __half* xh_b = g_xh + (size_t)b * (NCH * RES * RES * CH);
    const __half* wf_b = g_wf + (size_t)b * (NCH * 9 * COUT * CH);

    float acc[4][8][4];
    #pragma unroll
    for (int a = 0; a < 4; a++)
        #pragma unroll
        for (int j = 0; j < 8; j++)
            #pragma unroll
            for (int c = 0; c < 4; c++) acc[a][j][c] = 0.f;

    issue_chunk(0, 0, tid, h0, w0, s_in_u, s_w_u, xh_b, wf_b);
    cpa_commit();

    const uint32_t a_lane = s_in_u + (uint32_t)((wr * 130 + wc * 64 + (lane & 15)) * 48 + ((lane >> 4) << 4));
    const uint32_t b_lane = s_w_u  + (uint32_t)((wn * 64 + (lane & 15)) * 48 + ((lane >> 4) << 4));

    #pragma unroll 1
    for (int cc = 0; cc < NCH; cc++) {
        if (cc < NCH - 1) {
            issue_chunk(cc + 1, (cc + 1) & 1, tid, h0, w0, s_in_u, s_w_u, xh_b, wf_b);
            cpa_commit();
            asm volatile("cp.async.wait_group 1;\n");
        } else {
            asm volatile("cp.async.wait_group 0;\n");
        }
        __syncthreads();

        const uint32_t ab = a_lane + (cc & 1) * IN_BUF_B;
        const uint32_t bb = b_lane + (cc & 1) * W_BUF_B;
        #pragma unroll
        for (int tap = 0; tap < 9; tap++) {
            const int kh = tap / 3, kw = tap % 3;
            const uint32_t arow = ab + (uint32_t)(kh * 130 + kw) * 48;
            const uint32_t brow = bb + (uint32_t)tap * 6144;
            uint32_t af[4][4], bf[4][4];
            #pragma unroll
            for (int mi = 0; mi < 4; mi++) ldsm_x4(af[mi], arow + mi * 768);
            #pragma unroll
            for (int ni = 0; ni < 4; ni++) ldsm_x4(bf[ni], brow + ni * 768);
            #pragma unroll
            for (int mi = 0; mi < 4; mi++)
                #pragma unroll
                for (int ni = 0; ni < 4; ni++) {
                    mma16816(acc[mi][ni * 2],     af[mi], bf[ni][0], bf[ni][2]);
                    mma16816(acc[mi][ni * 2 + 1], af[mi], bf[ni][1], bf[ni][3]);
                }
        }
        __syncthreads();
    }

    // ---------------- epilogue ----------------
    const float ns = nstr[0];
    const float SQ2 = 1.4142135623730951f;

    #pragma unroll 1
    for (int r = 0; r < 2; r++) {
        if (wr == r) {
            const float* nrow = noise + (size_t)(h0 + r) * RES + w0;
            #pragma unroll
            for (int mi = 0; mi < 4; mi++) {
                int p0 = wc * 64 + mi * 16 + (lane >> 2);
                float nv0 = nrow[p0] * ns;
                float nv1 = nrow[p0 + 8] * ns;
                #pragma unroll
                for (int j = 0; j < 8; j++) {
                    int co0 = wn * 64 + j * 8 + (lane & 3) * 2;
                    float b0 = bias[co0], b1 = bias[co0 + 1];
                    float* a = acc[mi][j];
                    float v;
                    v = a[0] + nv0 + b0; v = (v >= 0.f) ? v : 0.2f * v; v *= SQ2;
                    s_epi[co0 * 132 + p0] = fminf(fmaxf(v, -256.f), 256.f);
                    v = a[1] + nv0 + b1; v = (v >= 0.f) ? v : 0.2f * v; v *= SQ2;
                    s_epi[(co0 + 1) * 132 + p0] = fminf(fmaxf(v, -256.f), 256.f);
                    v = a[2] + nv1 + b0; v = (v >= 0.f) ? v : 0.2f * v; v *= SQ2;
                    s_epi[co0 * 132 + p0 + 8] = fminf(fmaxf(v, -256.f), 256.f);
                    v = a[3] + nv1 + b1; v = (v >= 0.f) ? v : 0.2f * v; v *= SQ2;
                    s_epi[(co0 + 1) * 132 + p0 + 8] = fminf(fmaxf(v, -256.f), 256.f);
                }
            }
        }
        __syncthreads();
        {
            int co  = tid >> 1;
            int off = (tid & 1) * 64;
            float* dst = out + (((size_t)(b * COUT + co)) * RES + (h0 + r)) * RES + w0 + off;
            const float* sp = s_epi + co * 132 + off;
            #pragma unroll
            for (int q = 0; q < 64; q += 4)
                *((float4*)(dst + q)) = *((const float4*)(sp + q));
        }
        __syncthreads();
    }
}

// ---------------- launch: 4 launches so ncu (-s captures 4th) hits k_conv ------
extern "C" void kernel_launch(void* const* d_in, const int* in_sizes, int n_in,
                              void* d_out, int out_size) {
    const float* x     = (const float*)d_in[0];
    const float* w     = (const float*)d_in[1];
    const float* aw    = (const float*)d_in[2];
    const float* ab    = (const float*)d_in[3];
    const float* wt    = (const float*)d_in[4];
    const float* noise = (const float*)d_in[5];
    const float* nstr  = (const float*)d_in[6];
    const float* bias  = (const float*)d_in[7];
    float* out = (float*)d_out;

    k_sw<<<8 + (COUT * CIN) / 256, 256>>>(w, aw, ab, wt);
    k_fold2<<<BATCH * COUT, 128>>>(wt);

    dim3 hgrid(RES / 32, RES, BATCH);
    k_half<<<hgrid, 256>>>(x);

    cudaFuncSetAttribute(k_conv, cudaFuncAttributeMaxDynamicSharedMemorySize, SMEM_BYTES);
    dim3 grid(2, RES / 2, BATCH);
    k_conv<<<grid, 256, SMEM_BYTES>>>(noise, nstr, bias, out);
}